// round 17
// baseline (speedup 1.0000x reference)
#include <cuda_runtime.h>
#include <cuda_fp16.h>
#include <cstdint>

// Router_63900523430579 (GB300/sm_103): scores = x[32768,2048] @ W[64,2048]^T
// Two-kernel scheme:
//  prep: convert x -> fp16 and retile to [cta][chunk][row][cols] contiguous
//        blocks (XOR-swizzled) + pack W to fp16 fragment order.
//  fused GEMM: cp.async.bulk contiguous chunk loads -> fp16 m16n8k16 mma ->
//        top-2 epilogue, grid barrier, fp64 fixup + aux loss.
// out f32: [0,65536) top2 idx ; [65536,131072) top2 weights ; [131072] aux loss

#define KDIM   2048
#define NTOK   32768
#define NEXP   64
#define MTILE  128
#define NCTA   (NTOK / MTILE)          // 256
#define NTHR   512
#define CKF    128                     // K floats per chunk
#define NCHUNK (KDIM / CKF)            // 16
#define XCH    8192                    // x u32 per (cta,chunk): 128 rows * 64
#define WCH    4096                    // W u32 per chunk: 8 steps * 512
#define XCHB   (XCH * 4)               // 32768 B
#define WCHB   (WCH * 4)               // 16384 B
#define STAGEB (XCHB + WCHB)           // 49152 B
#define SMEM_REQ (2 * STAGEB)          // 98304 B -> 2 CTA/SM
#define DELTA1 3.5e-3f

__device__ int      g_done, g_done2, g_cnt1, g_cnt2;
__device__ uint32_t g_x16[NCTA * NCHUNK * XCH];     // 128 MB tiled fp16 x
__device__ uint32_t g_Wp16[NEXP * KDIM / 2];        // fp16x2 fragment-packed
__device__ float    g_part[NCTA * NEXP];
__device__ int      g_list1[NTOK], g_list2[NTOK];
__device__ unsigned g_cand[NTOK];

__device__ __forceinline__ void mma16(float* d, uint32_t a0, uint32_t a1,
                                      uint32_t a2, uint32_t a3,
                                      uint32_t b0, uint32_t b1) {
    asm volatile("mma.sync.aligned.m16n8k16.row.col.f32.f16.f16.f32 "
                 "{%0,%1,%2,%3},{%4,%5,%6,%7},{%8,%9},{%0,%1,%2,%3};"
                 : "+f"(d[0]), "+f"(d[1]), "+f"(d[2]), "+f"(d[3])
                 : "r"(a0), "r"(a1), "r"(a2), "r"(a3), "r"(b0), "r"(b1));
}
__device__ __forceinline__ uint32_t h2(float a, float b) {
    __half2 h = __floats2half2_rn(a, b);
    return *reinterpret_cast<uint32_t*>(&h);
}
#define MBARRIER_INIT(m, c) \
    asm volatile("mbarrier.init.shared.b64 [%0], %1;" \
                 :: "r"((uint32_t)(m)), "r"((uint32_t)(c)) : "memory")
#define MBARRIER_EXPECT_TX(m, b) \
    asm volatile("mbarrier.arrive.expect_tx.shared.b64 _, [%0], %1;" \
                 :: "r"((uint32_t)(m)), "r"((uint32_t)(b)) : "memory")
#define MBAR_WAIT(m, p) do { \
    uint32_t _m = (uint32_t)(m), _p = (uint32_t)(p), _d; \
    asm volatile("{\n\t.reg .pred q;\n\t" \
        "mbarrier.try_wait.parity.acquire.cta.shared::cta.b64 q, [%1], %2;\n\t" \
        "selp.b32 %0, 1, 0, q;\n\t}" : "=r"(_d) : "r"(_m), "r"(_p) : "memory"); \
    if (!_d) { \
        asm volatile("{\n\t.reg .pred P1;\n\t" \
            "WL_%=:\n\t" \
            "mbarrier.try_wait.parity.acquire.cta.shared::cta.b64 P1, [%0], %1, 0x989680;\n\t" \
            "@P1 bra.uni WD_%=;\n\t" \
            "bra.uni WL_%=;\n\t" \
            "WD_%=:\n\t}" :: "r"(_m), "r"(_p) : "memory"); \
    } } while (0)
__device__ __forceinline__ void bulk_load_1d(uint32_t dst, const void* src,
                                             uint32_t bytes, uint32_t mbar) {
    asm volatile("cp.async.bulk.shared::cluster.global.mbarrier::complete_tx::bytes "
                 "[%0], [%1], %2, [%3];"
                 :: "r"(dst), "l"(src), "r"(bytes), "r"(mbar) : "memory");
}

// ================= prep: retile x to fp16, pack W, reset =================
// x tile layout: g_x16[cta*131072 + chunk*8192 + r*64 + ((col) ^ 4*(r&7))]
//   where col = k-pair index 0..63 within the chunk.
// W pack (step S = 0..127): u = S*512 + j*64 + lane*2 + reg holds fp16x2
//   {W[e][kk],W[e][kk+1]}, e = j*8 + lane/4, kk = S*16 + (lane%4)*2 + reg*8.
__global__ void __launch_bounds__(256)
prep_kernel(const float* __restrict__ x, const float* __restrict__ W) {
    int b = blockIdx.x, tid = threadIdx.x;
    if (b < NCTA * NCHUNK * 2) {                       // x retile
        int cta = b >> 5, rem = b & 31;
        int chunk = rem >> 1, rh = rem & 1;
        int r = rh * 64 + (tid >> 2);                  // local row 0..127
        int q = tid & 3;                               // 32-float segment
        const float* p = x + ((size_t)cta * 128 + r) * KDIM + chunk * CKF + q * 32;
        float4 f[8];
        #pragma unroll
        for (int j = 0; j < 8; j++) f[j] = *(const float4*)(p + 4 * j);
        uint32_t* ob = g_x16 + (size_t)cta * (NCHUNK * XCH) + chunk * XCH + r * 64;
        int sw = 4 * (r & 7);
        #pragma unroll
        for (int m = 0; m < 4; m++) {
            uint4 v;
            v.x = h2(f[2 * m].x, f[2 * m].y);
            v.y = h2(f[2 * m].z, f[2 * m].w);
            v.z = h2(f[2 * m + 1].x, f[2 * m + 1].y);
            v.w = h2(f[2 * m + 1].z, f[2 * m + 1].w);
            *(uint4*)(ob + ((q * 16 + 4 * m) ^ sw)) = v;
        }
    } else if (b < NCTA * NCHUNK * 2 + 128) {          // W pack
        int wb = b - NCTA * NCHUNK * 2;
        #pragma unroll
        for (int t = 0; t < 2; t++) {
            int u = wb * 512 + tid * 2 + t;
            int S = u >> 9, rem = u & 511;
            int j = rem >> 6, ln2 = rem & 63;
            int lane = ln2 >> 1, reg = ln2 & 1;
            int e = j * 8 + (lane >> 2);
            int kk = S * 16 + (lane & 3) * 2 + reg * 8;
            g_Wp16[u] = h2(W[(size_t)e * KDIM + kk], W[(size_t)e * KDIM + kk + 1]);
        }
        if (wb == 0 && tid == 0) { g_done = 0; g_done2 = 0; g_cnt1 = 0; g_cnt2 = 0; }
    }
}

// ================= fused GEMM + epilogue + fixup + aux =================
__global__ void __launch_bounds__(NTHR, 2)
fused_kernel(const float* __restrict__ x, const float* __restrict__ W,
             float* __restrict__ out) {
    extern __shared__ float smf[];
    uint32_t* smu = (uint32_t*)smf;
    __shared__ __align__(8) unsigned long long mbar_st[2];
    const uint32_t smb = (uint32_t)__cvta_generic_to_shared(smf);
    const uint32_t mb0 = (uint32_t)__cvta_generic_to_shared(mbar_st);
    const int tid = threadIdx.x;
    const int wid = tid >> 5, lane = tid & 31;
    const int lq = lane & 3, lr = lane >> 2;
    const int tile = wid >> 1;          // m16 tile 0..7
    const int half = wid & 1;           // expert half
    const int r0 = tile * 16 + lr;
    const int sw = 4 * lr;              // swizzle (r&7 == lr for r0 and r0+8)

    // ---- PHASE A: GEMM ----
    if (tid == 0) { MBARRIER_INIT(mb0, 1); MBARRIER_INIT(mb0 + 8, 1); }
    __syncthreads();

    const uint32_t* xg = g_x16 + (size_t)blockIdx.x * (NCHUNK * XCH);
    auto issue_chunk = [&](int c) {
        int st = c & 1;
        uint32_t dst = smb + (uint32_t)st * STAGEB;
        MBARRIER_EXPECT_TX(mb0 + 8 * st, (uint32_t)STAGEB);
        bulk_load_1d(dst, xg + (size_t)c * XCH, XCHB, mb0 + 8 * st);
        bulk_load_1d(dst + XCHB, g_Wp16 + (size_t)c * WCH, WCHB, mb0 + 8 * st);
    };

    float acc[4][4];
    #pragma unroll
    for (int j = 0; j < 4; j++)
        #pragma unroll
        for (int v = 0; v < 4; v++) acc[j][v] = 0.0f;

    if (tid == 0) { issue_chunk(0); issue_chunk(1); }

    for (int c = 0; c < NCHUNK; c++) {
        const int st = c & 1;
        MBAR_WAIT(mb0 + 8 * st, (c >> 1) & 1);
        const uint32_t* xb = smu + st * (STAGEB / 4);
        const uint32_t* wb = xb + XCH;
        #pragma unroll
        for (int s = 0; s < 8; s++) {
            uint32_t a0 = xb[r0 * 64 + ((s * 8 + lq) ^ sw)];
            uint32_t a1 = xb[(r0 + 8) * 64 + ((s * 8 + lq) ^ sw)];
            uint32_t a2 = xb[r0 * 64 + ((s * 8 + 4 + lq) ^ sw)];
            uint32_t a3 = xb[(r0 + 8) * 64 + ((s * 8 + 4 + lq) ^ sw)];
            #pragma unroll
            for (int jj = 0; jj < 4; jj++) {
                const uint32_t* bp = wb + s * 512 + (half * 4 + jj) * 64 + lane * 2;
                mma16(acc[jj], a0, a1, a2, a3, bp[0], bp[1]);
            }
        }
        __syncthreads();
        if (tid == 0 && c + 2 < NCHUNK) issue_chunk(c + 2);
    }

    // ---- epilogue overlay: sc[128][65], mm[128], iz[128], red[8][64] ----
    float* sc = smf;
    float* mm = sc + 128 * 65;
    float* iz = mm + 128;
    float* red = iz + 128;

    #pragma unroll
    for (int jj = 0; jj < 4; jj++) {
        int cb = (half * 4 + jj) * 8;
        sc[r0 * 65 + cb + 2 * lq]           = acc[jj][0];
        sc[r0 * 65 + cb + 2 * lq + 1]       = acc[jj][1];
        sc[(r0 + 8) * 65 + cb + 2 * lq]     = acc[jj][2];
        sc[(r0 + 8) * 65 + cb + 2 * lq + 1] = acc[jj][3];
    }
    __syncthreads();

    if (tid < 128) {    // one token per thread: top-4, softmax, ambiguity routing
        const int t = tid;
        const float* row = sc + t * 65;
        float m[4] = {-3e38f, -3e38f, -3e38f, -3e38f};
        int   id[4] = {0, 0, 0, 0};
        #pragma unroll 8
        for (int e = 0; e < 64; e++) {
            float v = row[e];
            if (v > m[0])      { m[3]=m[2]; id[3]=id[2]; m[2]=m[1]; id[2]=id[1];
                                 m[1]=m[0]; id[1]=id[0]; m[0]=v; id[0]=e; }
            else if (v > m[1]) { m[3]=m[2]; id[3]=id[2]; m[2]=m[1]; id[2]=id[1];
                                 m[1]=v; id[1]=e; }
            else if (v > m[2]) { m[3]=m[2]; id[3]=id[2]; m[2]=v; id[2]=e; }
            else if (v > m[3]) { m[3]=v; id[3]=e; }
        }
        float Z = 0.0f;
        #pragma unroll 8
        for (int e = 0; e < 64; e++) Z += __expf(row[e] - m[0]);
        mm[t] = m[0];
        iz[t] = 1.0f / Z;

        float e2 = __expf(m[1] - m[0]);
        float w1 = 1.0f / (1.0f + e2);
        size_t T = (size_t)blockIdx.x * MTILE + t;
        out[2 * T]     = (float)id[0];
        out[2 * T + 1] = (float)id[1];
        out[2 * (size_t)NTOK + 2 * T]     = w1;
        out[2 * (size_t)NTOK + 2 * T + 1] = e2 * w1;

        if ((m[0] - m[1]) < DELTA1 || (m[1] - m[2]) < DELTA1) {
            if ((m[1] - m[3]) < DELTA1) {
                int q = atomicAdd(&g_cnt2, 1);
                g_list2[q] = (int)T;
            } else {
                int q = atomicAdd(&g_cnt1, 1);
                g_list1[q] = (int)T;
                g_cand[q] = (unsigned)id[0] | ((unsigned)id[1] << 8) |
                            ((unsigned)id[2] << 16) | ((unsigned)id[3] << 24);
            }
        }
    }
    __syncthreads();

    {   // deterministic per-CTA expert-usage partials (8 segs x 16 tokens)
        const int e = tid & 63, seg = tid >> 6;
        float s = 0.0f;
        for (int t = seg * 16; t < seg * 16 + 16; t++)
            s += __expf(sc[t * 65 + e] - mm[t]) * iz[t];
        red[seg * 64 + e] = s;
    }
    __syncthreads();
    if (tid < NEXP) {
        float s = 0.0f;
        #pragma unroll
        for (int g = 0; g < 8; g++) s += red[g * 64 + tid];
        g_part[blockIdx.x * NEXP + tid] = s;
    }

    // ---- grid-wide barrier ----
    __threadfence();
    __syncthreads();
    if (tid == 0) {
        atomicAdd(&g_done, 1);
        while (atomicAdd(&g_done, 0) < NCTA) __nanosleep(128);
    }
    __syncthreads();
    __threadfence();

    // ---- PHASE B ----
    if (blockIdx.x == 0) {   // aux loss
        const int e = tid & 63, seg = tid >> 6;      // 8 segs x 32 CTAs
        float s = 0.0f;
        for (int c = seg * 32; c < seg * 32 + 32; c++)
            s += g_part[c * NEXP + e];
        smf[tid] = s;
        __syncthreads();
        if (tid < 64) {
            float u = 0.0f;
            #pragma unroll
            for (int g = 0; g < 8; g++) u += smf[g * 64 + tid];
            u *= (1.0f / (float)NTOK);
            smf[512 + tid] = u * u;
        }
        __syncthreads();
        if (tid < 32) {
            float v = smf[512 + tid] + smf[512 + tid + 32];
            #pragma unroll
            for (int o = 16; o > 0; o >>= 1) v += __shfl_xor_sync(0xffffffffu, v, o);
            if (tid == 0) out[131072] = 64.0f * v;
        }
        __syncthreads();
    }

    // fp64 recompute of top-4 candidates: 4 token-groups x 4 candidate-warps
    {
        static __shared__ double sv[16];
        static __shared__ int    se[16];
        const int n = g_cnt1;
        const int grp = wid >> 2;                     // 0..3
        for (int bq = blockIdx.x; bq < n; bq += 4 * NCTA) {
            const int q = bq + grp * NCTA;
            const bool valid = (q < n);
            int tok = 0, e = 0;
            double s = 0.0;
            if (valid) {
                tok = g_list1[q];
                e = (int)((g_cand[q] >> (8 * (wid & 3))) & 255u);
                const float* xr = x + (size_t)tok * KDIM;
                const float* wr = W + (size_t)e * KDIM;
                double c0 = 0.0, c1 = 0.0;
                #pragma unroll 2
                for (int j = 0; j < 64; j += 2) {
                    c0 += (double)xr[(j + 0) * 32 + lane] * (double)wr[(j + 0) * 32 + lane];
                    c1 += (double)xr[(j + 1) * 32 + lane] * (double)wr[(j + 1) * 32 + lane];
                }
                s = c0 + c1;
            }
            #pragma unroll
            for (int o = 16; o > 0; o >>= 1) s += __shfl_xor_sync(0xffffffffu, s, o);
            if (lane == 0) { sv[wid] = s; se[wid] = e; }
            __syncthreads();
            if ((tid & 127) == 0) {
                const int g = tid >> 7;               // 0..3
                const int qq = bq + g * NCTA;
                if (qq < n) {
                    const int tk = g_list1[qq];
                    const double* v = sv + g * 4;
                    const int*    ee = se + g * 4;
                    int b1 = 0;
                    for (int k = 1; k < 4; k++)
                        if (v[k] > v[b1] || (v[k] == v[b1] && ee[k] < ee[b1])) b1 = k;
                    int b2 = (b1 == 0) ? 1 : 0;
                    for (int k = 0; k < 4; k++) {
                        if (k == b1) continue;
                        if (v[k] > v[b2] || (v[k] == v[b2] && ee[k] < ee[b2])) b2 = k;
                    }
                    double e2 = exp(v[b2] - v[b1]);
                    double w1 = 1.0 / (1.0 + e2);
                    out[2 * (size_t)tk]     = (float)ee[b1];
                    out[2 * (size_t)tk + 1] = (float)ee[b2];
                    out[2 * (size_t)NTOK + 2 * (size_t)tk]     = (float)w1;
                    out[2 * (size_t)NTOK + 2 * (size_t)tk + 1] = (float)(e2 * w1);
                }
            }
            __syncthreads();
        }
    }

    // rare full-64 fp64 tokens: warp wid -> experts wid*4..wid*4+3
    {
        static __shared__ double sh[64];
        const int n2 = g_cnt2;
        for (int q = blockIdx.x; q < n2; q += NCTA) {
            const int tok = g_list2[q];
            const float* xr = x + (size_t)tok * KDIM;
            #pragma unroll 1
            for (int e4 = 0; e4 < 4; e4++) {
                const int e = wid * 4 + e4;
                const float* wr = W + (size_t)e * KDIM;
                double c0 = 0.0, c1 = 0.0;
                #pragma unroll 2
                for (int j = 0; j < 64; j += 2) {
                    c0 += (double)xr[(j + 0) * 32 + lane] * (double)wr[(j + 0) * 32 + lane];
                    c1 += (double)xr[(j + 1) * 32 + lane] * (double)wr[(j + 1) * 32 + lane];
                }
                double s = c0 + c1;
                #pragma unroll
                for (int o = 16; o > 0; o >>= 1) s += __shfl_xor_sync(0xffffffffu, s, o);
                if (lane == 0) sh[e] = s;
            }
            __syncthreads();
            if (tid == 0) {
                double m1 = -1e300, m2 = -1e300; int i1 = 0, i2 = 0;
                for (int e = 0; e < 64; e++)
                    if (sh[e] > m1) { m1 = sh[e]; i1 = e; }
                for (int e = 0; e < 64; e++) {
                    if (e == i1) continue;
                    if (sh[e] > m2) { m2 = sh[e]; i2 = e; }
                }
                double e2 = exp(m2 - m1);
                double w1 = 1.0 / (1.0 + e2);
                out[2 * (size_t)tok]     = (float)i1;
                out[2 * (size_t)tok + 1] = (float)i2;
                out[2 * (size_t)NTOK + 2 * (size_t)tok]     = (float)w1;
                out[2 * (size_t)NTOK + 2 * (size_t)tok + 1] = (float)(e2 * w1);
            }
            __syncthreads();
        }
    }

    // ---- PHASE C: reset for next graph replay ----
    __syncthreads();
    if (tid == 0) {
        __threadfence();
        int v = atomicAdd(&g_done2, 1);
        if (v == NCTA - 1) {
            g_done = 0; g_done2 = 0; g_cnt1 = 0; g_cnt2 = 0;
            __threadfence();
        }
    }
}

extern "C" void kernel_launch(void* const* d_in, const int* in_sizes, int n_in,
                              void* d_out, int out_size) {
    const float* x = (const float*)d_in[0];
    const float* W = (const float*)d_in[1];
    float* out = (float*)d_out;
    cudaFuncSetAttribute(fused_kernel, cudaFuncAttributeMaxDynamicSharedMemorySize,
                         SMEM_REQ);
    prep_kernel<<<NCTA * NCHUNK * 2 + 128, 256>>>(x, W);
    fused_kernel<<<NCTA, NTHR, SMEM_REQ>>>(x, W, out);
}